// round 8
// baseline (speedup 1.0000x reference)
#include <cuda_runtime.h>
#include <cuda_bf16.h>
#include <cstdint>
#include <cstddef>

#define D_IN  12544
#define D_HID 1024
#define MAXN  16000

// ---------------- device scratch (allocation-free rule) ----------------
__device__ __align__(1024) int8_t g_Xa1[(size_t)MAXN * D_IN];
__device__ __align__(1024) int8_t g_Xa0[(size_t)MAXN * D_IN];
__device__ __align__(1024) int8_t g_W1a1[(size_t)D_HID * D_IN];   // [N][K]
__device__ __align__(1024) int8_t g_W1a0[(size_t)D_HID * D_IN];
__device__ __align__(1024) int8_t g_W2a1[(size_t)D_HID * D_HID];
__device__ __align__(1024) int8_t g_W2a0[(size_t)D_HID * D_HID];
__device__ __align__(1024) int8_t g_h1a1[(size_t)MAXN * D_HID];
__device__ __align__(1024) int8_t g_h1a0[(size_t)MAXN * D_HID];
__device__ float g_h2[(size_t)MAXN * D_HID];

// ---------------- scales (16-bit fixed point, clamped to +-32639) ----------------
#define QMAX    32639
#define SX      (6.5f / 32639.f)
#define INV_SX  (32639.f / 6.5f)
#define SW1     ((1.f / 112.f) / 32639.f)
#define SW2     ((1.f / 32.f) / 32639.f)
#define SH      (4.f / 32639.f)
#define INV_SH  (32639.f / 4.f)

// ---------------- asm helpers ----------------
__device__ __forceinline__ uint32_t smem_u32(const void* p) {
    uint32_t a;
    asm("{ .reg .u64 t; cvta.to.shared.u64 t, %1; cvt.u32.u64 %0, t; }" : "=r"(a) : "l"(p));
    return a;
}
__device__ __forceinline__ void cp16(uint32_t dst, const void* src) {
    asm volatile("cp.async.cg.shared.global [%0], [%1], 16;" :: "r"(dst), "l"(src));
}
__device__ __forceinline__ void cp_commit() {
    asm volatile("cp.async.commit_group;" ::: "memory");
}
template <int N>
__device__ __forceinline__ void cp_wait() {
    asm volatile("cp.async.wait_group %0;" :: "n"(N) : "memory");
}
__device__ __forceinline__ void ldm_x4(uint32_t* r, uint32_t addr) {
    asm volatile("ldmatrix.sync.aligned.m8n8.x4.shared.b16 {%0,%1,%2,%3}, [%4];"
                 : "=r"(r[0]), "=r"(r[1]), "=r"(r[2]), "=r"(r[3]) : "r"(addr));
}
__device__ __forceinline__ void imma16832(int* c, const uint32_t* a, uint32_t b0, uint32_t b1) {
    asm volatile(
        "mma.sync.aligned.m16n8k32.row.col.s32.s8.s8.s32 "
        "{%0,%1,%2,%3}, {%4,%5,%6,%7}, {%8,%9}, {%0,%1,%2,%3};"
        : "+r"(c[0]), "+r"(c[1]), "+r"(c[2]), "+r"(c[3])
        : "r"(a[0]), "r"(a[1]), "r"(a[2]), "r"(a[3]), "r"(b0), "r"(b1));
}

// quantize fp32 -> int16 (clamped) -> split into a1*256 + a0
__device__ __forceinline__ void q16(float x, float inv_s, int8_t& hi, int8_t& lo) {
    int q = __float2int_rn(x * inv_s);
    q = max(-QMAX, min(QMAX, q));
    int h = (q + 128) >> 8;
    hi = (int8_t)h;
    lo = (int8_t)(q - (h << 8));
}

// ---------------- GEMM: C[M,N] = act(s*(A @ B^T) + bias), int8 x3 fixed-point ----------------
// CTA tile BM=64, BN=128, BK=64 bytes. 2-stage cp.async, 2 CTAs/SM.
// 8 warps (2 M x 4 N), warp tile 32x32. IMMA m16n8k32.
#define LDSB      80                    // smem row stride in bytes (64 + 16 pad)
#define TILE_AB   (64 * LDSB)           // 5120  B per [64][64B] tile
#define TILE_BB   (128 * LDSB)          // 10240 B per [128][64B] tile
#define OFF_A1    0
#define OFF_A0    (TILE_AB)
#define OFF_B1    (2 * TILE_AB)
#define OFF_B0    (2 * TILE_AB + TILE_BB)
#define STAGE_B   (2 * TILE_AB + 2 * TILE_BB)     // 30720
#define SM_TOTAL  (2 * STAGE_B)                    // 61440 -> 2 CTAs/SM

__device__ __forceinline__ void load_tileA(uint32_t sdst, const int8_t* __restrict__ g,
                                           int row0, int K, int k0, int tid)
{
    // 64 rows x 64B = 256 chunks of 16B; 256 threads -> 1 each
    const int8_t* gb = g + (size_t)row0 * K + k0;
    const int r = tid >> 2;
    const int c = tid & 3;
    cp16(sdst + r * LDSB + c * 16, gb + (size_t)r * K + c * 16);
}
__device__ __forceinline__ void load_tileB(uint32_t sdst, const int8_t* __restrict__ g,
                                           int row0, int K, int k0, int tid)
{
    // 128 rows x 64B = 512 chunks; 2 each
    const int8_t* gb = g + (size_t)row0 * K + k0;
#pragma unroll
    for (int p = 0; p < 2; p++) {
        const int r = (tid >> 2) + p * 64;
        const int c = tid & 3;
        cp16(sdst + r * LDSB + c * 16, gb + (size_t)r * K + c * 16);
    }
}

template <int WRITE_Q>
__global__ __launch_bounds__(256, 2)
void gemm_imma_x3(const int8_t* __restrict__ Aa1, const int8_t* __restrict__ Aa0,
                  const int8_t* __restrict__ Ba1, const int8_t* __restrict__ Ba0,
                  const float* __restrict__ bias, float oscale,
                  int8_t* __restrict__ Ca1, int8_t* __restrict__ Ca0,
                  float* __restrict__ Cf,
                  int K, int N)
{
    extern __shared__ char smem[];
    const uint32_t sb = smem_u32(smem);
    const int tid  = threadIdx.x;
    const int wid  = tid >> 5;
    const int lane = tid & 31;
    const int wm   = wid & 1;        // 0..1 (M)
    const int wn   = wid >> 1;       // 0..3 (N)

    const int bm = blockIdx.y * 64;
    const int bn = blockIdx.x * 128;
    const int NK = K / 64;

    int S11[2][4][4], Sc[2][4][4];
#pragma unroll
    for (int mt = 0; mt < 2; mt++)
#pragma unroll
        for (int nb = 0; nb < 4; nb++)
#pragma unroll
            for (int q = 0; q < 4; q++) { S11[mt][nb][q] = 0; Sc[mt][nb][q] = 0; }

    // prologue: prefetch stage 0
    {
        load_tileA(sb + OFF_A1, Aa1, bm, K, 0, tid);
        load_tileA(sb + OFF_A0, Aa0, bm, K, 0, tid);
        load_tileB(sb + OFF_B1, Ba1, bn, K, 0, tid);
        load_tileB(sb + OFF_B0, Ba0, bn, K, 0, tid);
        cp_commit();
    }

    // ldmatrix lane addressing (byte offsets; 1 "half" = 2 int8)
    const uint32_t a_lane_off = (lane & 15) * LDSB + (lane >> 4) * 16;
    const uint32_t b_lane_off = (((lane >> 4) * 8) + (lane & 7)) * LDSB + ((lane >> 3) & 1) * 16;
    const uint32_t a_base_off = (wm * 32) * LDSB;
    const uint32_t b_base_off = (wn * 32) * LDSB;

    for (int c = 0; c < NK; c++) {
        cp_wait<0>();
        __syncthreads();

        const int pf = c + 1;
        if (pf < NK) {
            const uint32_t st = sb + (pf & 1) * STAGE_B;
            load_tileA(st + OFF_A1, Aa1, bm, K, pf * 64, tid);
            load_tileA(st + OFF_A0, Aa0, bm, K, pf * 64, tid);
            load_tileB(st + OFF_B1, Ba1, bn, K, pf * 64, tid);
            load_tileB(st + OFF_B0, Ba0, bn, K, pf * 64, tid);
        }
        cp_commit();

        const uint32_t st = sb + (c & 1) * STAGE_B;
        const uint32_t sA1 = st + OFF_A1 + a_base_off + a_lane_off;
        const uint32_t sA0 = st + OFF_A0 + a_base_off + a_lane_off;
        const uint32_t sB1 = st + OFF_B1 + b_base_off + b_lane_off;
        const uint32_t sB0 = st + OFF_B0 + b_base_off + b_lane_off;

#pragma unroll
        for (int kk = 0; kk < 2; kk++) {
            const uint32_t ko = kk * 32;   // 32 bytes of K per k-step
            uint32_t a1f[2][4], a0f[2][4];
#pragma unroll
            for (int mt = 0; mt < 2; mt++) {
                ldm_x4(a1f[mt], sA1 + mt * 16 * LDSB + ko);
                ldm_x4(a0f[mt], sA0 + mt * 16 * LDSB + ko);
            }
#pragma unroll
            for (int pp = 0; pp < 2; pp++) {
                uint32_t b1f[4], b0f[4];
                ldm_x4(b1f, sB1 + pp * 16 * LDSB + ko);
                ldm_x4(b0f, sB0 + pp * 16 * LDSB + ko);
                // product-major: a1*b1 (main), then a1*b0, then a0*b1 (cross)
#pragma unroll
                for (int mt = 0; mt < 2; mt++)
#pragma unroll
                    for (int h = 0; h < 2; h++)
                        imma16832(S11[mt][pp * 2 + h], a1f[mt], b1f[h * 2], b1f[h * 2 + 1]);
#pragma unroll
                for (int mt = 0; mt < 2; mt++)
#pragma unroll
                    for (int h = 0; h < 2; h++)
                        imma16832(Sc[mt][pp * 2 + h], a1f[mt], b0f[h * 2], b0f[h * 2 + 1]);
#pragma unroll
                for (int mt = 0; mt < 2; mt++)
#pragma unroll
                    for (int h = 0; h < 2; h++)
                        imma16832(Sc[mt][pp * 2 + h], a0f[mt], b1f[h * 2], b1f[h * 2 + 1]);
            }
        }
        __syncthreads();
    }

    // ---------------- epilogue: scale + bias + ReLU (+ requantize) ----------------
#pragma unroll
    for (int mt = 0; mt < 2; mt++) {
        const int row0 = bm + wm * 32 + mt * 16 + (lane >> 2);
#pragma unroll
        for (int nb = 0; nb < 4; nb++) {
            const int col = bn + wn * 32 + nb * 8 + (lane & 3) * 2;
            const float bx = bias[col];
            const float by = bias[col + 1];
            float y[4];
#pragma unroll
            for (int q = 0; q < 4; q++) {
                const float t = fmaf(65536.f, (float)S11[mt][nb][q], 256.f * (float)Sc[mt][nb][q]);
                y[q] = fmaf(t, oscale, (q & 1) ? by : bx);
                y[q] = fmaxf(y[q], 0.0f);
            }
            if (WRITE_Q) {
                int8_t h0, l0, h1, l1, h2, l2, h3, l3;
                q16(y[0], INV_SH, h0, l0);
                q16(y[1], INV_SH, h1, l1);
                q16(y[2], INV_SH, h2, l2);
                q16(y[3], INV_SH, h3, l3);
                *(char2*)(Ca1 + (size_t)row0 * N + col)       = make_char2(h0, h1);
                *(char2*)(Ca0 + (size_t)row0 * N + col)       = make_char2(l0, l1);
                *(char2*)(Ca1 + (size_t)(row0 + 8) * N + col) = make_char2(h2, h3);
                *(char2*)(Ca0 + (size_t)(row0 + 8) * N + col) = make_char2(l2, l3);
            } else {
                *(float2*)(Cf + (size_t)row0 * N + col)       = make_float2(y[0], y[1]);
                *(float2*)(Cf + (size_t)(row0 + 8) * N + col) = make_float2(y[2], y[3]);
            }
        }
    }
}

// ---------------- quantization kernels ----------------
__global__ __launch_bounds__(256)
void quant_x(const float* __restrict__ in, int8_t* __restrict__ a1,
             int8_t* __restrict__ a0, size_t n4)
{
    size_t i = (size_t)blockIdx.x * blockDim.x + threadIdx.x;
    if (i >= n4) return;
    float4 v = ((const float4*)in)[i];
    int8_t h0, l0, h1, l1, h2, l2, h3, l3;
    q16(v.x, INV_SX, h0, l0);
    q16(v.y, INV_SX, h1, l1);
    q16(v.z, INV_SX, h2, l2);
    q16(v.w, INV_SX, h3, l3);
    ((char4*)a1)[i] = make_char4(h0, h1, h2, h3);
    ((char4*)a0)[i] = make_char4(l0, l1, l2, l3);
}

// in: [K][N] fp32 row-major -> out a1/a0: [N][K] int8 row-major
__global__ __launch_bounds__(256)
void quant_transpose_w(const float* __restrict__ in, int8_t* __restrict__ a1,
                       int8_t* __restrict__ a0, int K, int N, float inv_s)
{
    __shared__ float t[32][33];
    const int k0 = blockIdx.y * 32;
    const int n0 = blockIdx.x * 32;
    const int tx = threadIdx.x;
    const int ty = threadIdx.y;
#pragma unroll
    for (int r = 0; r < 4; r++) {
        const int k = k0 + ty * 4 + r;
        t[ty * 4 + r][tx] = in[(size_t)k * N + n0 + tx];
    }
    __syncthreads();
#pragma unroll
    for (int r = 0; r < 4; r++) {
        const int n = n0 + ty * 4 + r;
        int8_t h, l;
        q16(t[tx][ty * 4 + r], inv_s, h, l);
        a1[(size_t)n * K + k0 + tx] = h;
        a0[(size_t)n * K + k0 + tx] = l;
    }
}

// ---------------- heads ----------------
__global__ __launch_bounds__(256)
void heads_kernel(const float* __restrict__ H,
                  const float* __restrict__ Wc, const float* __restrict__ bc,
                  const float* __restrict__ Wr, const float* __restrict__ br,
                  float* __restrict__ out, int M)
{
    const int warp = (blockIdx.x * blockDim.x + threadIdx.x) >> 5;
    const int lane = threadIdx.x & 31;
    if (warp >= M) return;

    const float* __restrict__ h = H + (size_t)warp * D_HID;
    float acc[16];
#pragma unroll
    for (int c = 0; c < 16; c++) acc[c] = 0.0f;

    for (int k = lane; k < D_HID; k += 32) {
        const float x = h[k];
        const float* wc = Wc + (size_t)k * 4;
#pragma unroll
        for (int c = 0; c < 4; c++) acc[c] = fmaf(x, wc[c], acc[c]);
        const float* wr = Wr + (size_t)k * 12;
#pragma unroll
        for (int c = 0; c < 12; c++) acc[4 + c] = fmaf(x, wr[c], acc[4 + c]);
    }
#pragma unroll
    for (int c = 0; c < 16; c++)
#pragma unroll
        for (int off = 16; off > 0; off >>= 1)
            acc[c] += __shfl_xor_sync(0xffffffffu, acc[c], off);

    if (lane < 4) {
        out[(size_t)warp * 4 + lane] = acc[lane] + bc[lane];
    } else if (lane < 16) {
        out[(size_t)M * 4 + (size_t)warp * 12 + (lane - 4)] = acc[lane] + br[lane - 4];
    }
}

// ---------------- host ----------------
extern "C" void kernel_launch(void* const* d_in, const int* in_sizes, int n_in,
                              void* d_out, int out_size)
{
    const float* X  = (const float*)d_in[0];
    const float* W1 = (const float*)d_in[1];
    const float* b1 = (const float*)d_in[2];
    const float* W2 = (const float*)d_in[3];
    const float* b2 = (const float*)d_in[4];
    const float* Wc = (const float*)d_in[5];
    const float* bc = (const float*)d_in[6];
    const float* Wr = (const float*)d_in[7];
    const float* br = (const float*)d_in[8];
    float* out = (float*)d_out;

    const int M = in_sizes[0] / D_IN;   // 16000

    int8_t *Xa1, *Xa0, *W1a1, *W1a0, *W2a1, *W2a0, *h1a1, *h1a0;
    float* h2;
    cudaGetSymbolAddress((void**)&Xa1, g_Xa1);
    cudaGetSymbolAddress((void**)&Xa0, g_Xa0);
    cudaGetSymbolAddress((void**)&W1a1, g_W1a1);
    cudaGetSymbolAddress((void**)&W1a0, g_W1a0);
    cudaGetSymbolAddress((void**)&W2a1, g_W2a1);
    cudaGetSymbolAddress((void**)&W2a0, g_W2a0);
    cudaGetSymbolAddress((void**)&h1a1, g_h1a1);
    cudaGetSymbolAddress((void**)&h1a0, g_h1a0);
    cudaGetSymbolAddress((void**)&h2, g_h2);

    // quantization
    {
        const size_t n4 = (size_t)M * D_IN / 4;
        quant_x<<<(unsigned)((n4 + 255) / 256), 256>>>(X, Xa1, Xa0, n4);
        dim3 tb(32, 8);
        quant_transpose_w<<<dim3(D_HID / 32, D_IN / 32), tb>>>(W1, W1a1, W1a0, D_IN, D_HID, 1.0f / SW1);
        quant_transpose_w<<<dim3(D_HID / 32, D_HID / 32), tb>>>(W2, W2a1, W2a0, D_HID, D_HID, 1.0f / SW2);
    }

    cudaFuncSetAttribute(gemm_imma_x3<1>, cudaFuncAttributeMaxDynamicSharedMemorySize, SM_TOTAL);
    cudaFuncSetAttribute(gemm_imma_x3<0>, cudaFuncAttributeMaxDynamicSharedMemorySize, SM_TOTAL);

    dim3 grid(D_HID / 128, M / 64);     // (8, 250) = 2000 CTAs
    gemm_imma_x3<1><<<grid, 256, SM_TOTAL>>>(Xa1, Xa0, W1a1, W1a0, b1, SX * SW1,
                                             h1a1, h1a0, nullptr, D_IN, D_HID);
    gemm_imma_x3<0><<<grid, 256, SM_TOTAL>>>(h1a1, h1a0, W2a1, W2a0, b2, SH * SW2,
                                             nullptr, nullptr, h2, D_HID, D_HID);

    const int threads = 256;
    const int blocks = (M * 32 + threads - 1) / threads;
    heads_kernel<<<blocks, threads>>>(h2, Wc, bc, Wr, br, out, M);
}

// round 9
// speedup vs baseline: 2.5517x; 2.5517x over previous
#include <cuda_runtime.h>
#include <cuda_bf16.h>
#include <cstdint>
#include <cstddef>

#define D_IN  12544
#define D_HID 1024
#define MAXN  16000

// ---------------- device scratch (allocation-free rule) ----------------
__device__ __align__(1024) __nv_bfloat16 g_Xhi[(size_t)MAXN * D_IN];
__device__ __align__(1024) __nv_bfloat16 g_Xlo[(size_t)MAXN * D_IN];
__device__ __align__(1024) __nv_bfloat16 g_W1hi[(size_t)D_HID * D_IN];  // [N][K]
__device__ __align__(1024) __nv_bfloat16 g_W1lo[(size_t)D_HID * D_IN];
__device__ __align__(1024) __nv_bfloat16 g_W2hi[(size_t)D_HID * D_HID];
__device__ __align__(1024) __nv_bfloat16 g_W2lo[(size_t)D_HID * D_HID];
__device__ __align__(1024) __nv_bfloat16 g_h1hi[(size_t)MAXN * D_HID];
__device__ __align__(1024) __nv_bfloat16 g_h1lo[(size_t)MAXN * D_HID];
__device__ float g_h2[(size_t)MAXN * D_HID];

// ---------------- asm helpers ----------------
__device__ __forceinline__ uint32_t smem_u32(const void* p) {
    uint32_t a;
    asm("{ .reg .u64 t; cvta.to.shared.u64 t, %1; cvt.u32.u64 %0, t; }" : "=r"(a) : "l"(p));
    return a;
}
__device__ __forceinline__ void cp16(uint32_t dst, const void* src) {
    asm volatile("cp.async.cg.shared.global [%0], [%1], 16;" :: "r"(dst), "l"(src));
}
__device__ __forceinline__ void cp_commit() {
    asm volatile("cp.async.commit_group;" ::: "memory");
}
template <int N>
__device__ __forceinline__ void cp_wait() {
    asm volatile("cp.async.wait_group %0;" :: "n"(N) : "memory");
}
__device__ __forceinline__ void ldm_x4(uint32_t* r, uint32_t addr) {
    asm volatile("ldmatrix.sync.aligned.m8n8.x4.shared.b16 {%0,%1,%2,%3}, [%4];"
                 : "=r"(r[0]), "=r"(r[1]), "=r"(r[2]), "=r"(r[3]) : "r"(addr));
}
__device__ __forceinline__ void mma16816(float* c, const uint32_t* a, uint32_t b0, uint32_t b1) {
    asm volatile(
        "mma.sync.aligned.m16n8k16.row.col.f32.bf16.bf16.f32 "
        "{%0,%1,%2,%3}, {%4,%5,%6,%7}, {%8,%9}, {%0,%1,%2,%3};"
        : "+f"(c[0]), "+f"(c[1]), "+f"(c[2]), "+f"(c[3])
        : "r"(a[0]), "r"(a[1]), "r"(a[2]), "r"(a[3]), "r"(b0), "r"(b1));
}

// ---------------- GEMM: C[M,N] = act(A[M,K] @ B[N,K]^T + bias), bf16 hi/lo x3 ----------------
// CTA tile BM=128, BN=128, BK=32. 4-stage cp.async pipeline, prefetch distance 2,
// __syncthreads every 2 iterations. 16 warps (4 M x 4 N), warp tile 32x32.
#define LDS       40                    // smem stride in halves (80B) - conflict free
#define TILE_B    (128 * LDS * 2)       // 10240 B per [128][32] bf16 tile
#define OFF_AHI   0
#define OFF_ALO   (TILE_B)
#define OFF_BHI   (2 * TILE_B)
#define OFF_BLO   (3 * TILE_B)
#define STAGE_B   (4 * TILE_B)          // 40960
#define NSTAGE    4
#define SM_TOTAL  (NSTAGE * STAGE_B)    // 163840 -> 1 CTA/SM

__device__ __forceinline__ void load_tile(uint32_t sdst, const __nv_bfloat16* __restrict__ g,
                                          int row0, int K, int k0, int tid)
{
    // 512 threads, 512 x 16B chunks: one chunk per thread
    const char* gb = (const char*)(g + (size_t)row0 * K + k0);
    const int r = tid >> 2;
    const int c = tid & 3;
    cp16(sdst + r * (LDS * 2) + c * 16, gb + (size_t)r * K * 2 + c * 16);
}

template <int WRITE_HILO>
__global__ __launch_bounds__(512, 1)
void gemm_mma_x3(const __nv_bfloat16* __restrict__ Ahi, const __nv_bfloat16* __restrict__ Alo,
                 const __nv_bfloat16* __restrict__ Bhi, const __nv_bfloat16* __restrict__ Blo,
                 const float* __restrict__ bias,
                 __nv_bfloat16* __restrict__ Chi, __nv_bfloat16* __restrict__ Clo,
                 float* __restrict__ Cf,
                 int K, int N)
{
    extern __shared__ char smem[];
    const uint32_t sb = smem_u32(smem);
    const int tid  = threadIdx.x;
    const int wid  = tid >> 5;
    const int lane = tid & 31;
    const int wm   = wid & 3;        // 0..3 (M)
    const int wn   = wid >> 2;       // 0..3 (N)

    const int bm = blockIdx.y * 128;
    const int bn = blockIdx.x * 128;
    const int NK = K / 32;           // even for both GEMMs (392, 32)

    float acc[2][4][4];
#pragma unroll
    for (int mt = 0; mt < 2; mt++)
#pragma unroll
        for (int nb = 0; nb < 4; nb++)
#pragma unroll
            for (int q = 0; q < 4; q++) acc[mt][nb][q] = 0.0f;

    // prologue: prefetch stages 0, 1 (prefetch distance = 2)
#pragma unroll
    for (int s = 0; s < 2; s++) {
        const uint32_t st = sb + s * STAGE_B;
        load_tile(st + OFF_AHI, Ahi, bm, K, s * 32, tid);
        load_tile(st + OFF_ALO, Alo, bm, K, s * 32, tid);
        load_tile(st + OFF_BHI, Bhi, bn, K, s * 32, tid);
        load_tile(st + OFF_BLO, Blo, bn, K, s * 32, tid);
        cp_commit();
    }

    // ldmatrix lane addressing (within-tile offsets, in bytes)
    const uint32_t a_lane_off = ((lane & 15) * LDS + (lane >> 4) * 8) * 2;
    const uint32_t b_lane_off = ((((lane >> 4) * 8) + (lane & 7)) * LDS + (((lane >> 3) & 1) * 8)) * 2;
    const uint32_t a_base_off = (wm * 32) * (LDS * 2);
    const uint32_t b_base_off = (wn * 32) * (LDS * 2);

    for (int c = 0; c < NK; c++) {
        // barrier only on even iterations: makes stages c and c+1 visible,
        // and guarantees stage (c+2)%4 / (c+3)%4 buffers are free to overwrite
        if ((c & 1) == 0) {
            cp_wait<0>();
            __syncthreads();
        }

        // prefetch stage c+2 (buffer (c+2)%4, last read at iter c-2)
        const int pf = c + 2;
        if (pf < NK) {
            const uint32_t st = sb + (pf & 3) * STAGE_B;
            load_tile(st + OFF_AHI, Ahi, bm, K, pf * 32, tid);
            load_tile(st + OFF_ALO, Alo, bm, K, pf * 32, tid);
            load_tile(st + OFF_BHI, Bhi, bn, K, pf * 32, tid);
            load_tile(st + OFF_BLO, Blo, bn, K, pf * 32, tid);
        }
        cp_commit();

        const uint32_t st = sb + (c & 3) * STAGE_B;
        const uint32_t sAh = st + OFF_AHI + a_base_off + a_lane_off;
        const uint32_t sAl = st + OFF_ALO + a_base_off + a_lane_off;
        const uint32_t sBh = st + OFF_BHI + b_base_off + b_lane_off;
        const uint32_t sBl = st + OFF_BLO + b_base_off + b_lane_off;

#pragma unroll
        for (int kk = 0; kk < 2; kk++) {
            const uint32_t ko = kk * 16 * 2;
            uint32_t ah[2][4], al[2][4];
#pragma unroll
            for (int mt = 0; mt < 2; mt++) {
                ldm_x4(ah[mt], sAh + mt * 16 * (LDS * 2) + ko);
                ldm_x4(al[mt], sAl + mt * 16 * (LDS * 2) + ko);
            }
            uint32_t bh[2][4], bl[2][4];   // pi covers cols pi*16..pi*16+15
#pragma unroll
            for (int pi = 0; pi < 2; pi++) {
                ldm_x4(bh[pi], sBh + pi * 16 * (LDS * 2) + ko);
                ldm_x4(bl[pi], sBl + pi * 16 * (LDS * 2) + ko);
            }
            // product-major: 8 independent MMAs per product
#pragma unroll
            for (int mt = 0; mt < 2; mt++)
#pragma unroll
                for (int pi = 0; pi < 2; pi++)
#pragma unroll
                    for (int h = 0; h < 2; h++)
                        mma16816(acc[mt][pi * 2 + h], ah[mt], bh[pi][h * 2], bh[pi][h * 2 + 1]);
#pragma unroll
            for (int mt = 0; mt < 2; mt++)
#pragma unroll
                for (int pi = 0; pi < 2; pi++)
#pragma unroll
                    for (int h = 0; h < 2; h++)
                        mma16816(acc[mt][pi * 2 + h], ah[mt], bl[pi][h * 2], bl[pi][h * 2 + 1]);
#pragma unroll
            for (int mt = 0; mt < 2; mt++)
#pragma unroll
                for (int pi = 0; pi < 2; pi++)
#pragma unroll
                    for (int h = 0; h < 2; h++)
                        mma16816(acc[mt][pi * 2 + h], al[mt], bh[pi][h * 2], bh[pi][h * 2 + 1]);
        }
    }

    // ---------------- epilogue: bias + ReLU ----------------
#pragma unroll
    for (int mt = 0; mt < 2; mt++) {
        const int row0 = bm + wm * 32 + mt * 16 + (lane >> 2);
#pragma unroll
        for (int nb = 0; nb < 4; nb++) {
            const int col = bn + wn * 32 + nb * 8 + (lane & 3) * 2;
            const float bx = bias[col];
            const float by = bias[col + 1];
            float y0 = fmaxf(acc[mt][nb][0] + bx, 0.0f);
            float y1 = fmaxf(acc[mt][nb][1] + by, 0.0f);
            float y2 = fmaxf(acc[mt][nb][2] + bx, 0.0f);
            float y3 = fmaxf(acc[mt][nb][3] + by, 0.0f);
            if (WRITE_HILO) {
                __nv_bfloat16 h0 = __float2bfloat16(y0), h1 = __float2bfloat16(y1);
                __nv_bfloat16 h2 = __float2bfloat16(y2), h3 = __float2bfloat16(y3);
                __nv_bfloat16 l0 = __float2bfloat16(y0 - __bfloat162float(h0));
                __nv_bfloat16 l1 = __float2bfloat16(y1 - __bfloat162float(h1));
                __nv_bfloat16 l2 = __float2bfloat16(y2 - __bfloat162float(h2));
                __nv_bfloat16 l3 = __float2bfloat16(y3 - __bfloat162float(h3));
                *(__nv_bfloat162*)(Chi + (size_t)row0 * N + col)       = __nv_bfloat162(h0, h1);
                *(__nv_bfloat162*)(Chi + (size_t)(row0 + 8) * N + col) = __nv_bfloat162(h2, h3);
                *(__nv_bfloat162*)(Clo + (size_t)row0 * N + col)       = __nv_bfloat162(l0, l1);
                *(__nv_bfloat162*)(Clo + (size_t)(row0 + 8) * N + col) = __nv_bfloat162(l2, l3);
            } else {
                *(float2*)(Cf + (size_t)row0 * N + col)       = make_float2(y0, y1);
                *(float2*)(Cf + (size_t)(row0 + 8) * N + col) = make_float2(y2, y3);
            }
        }
    }
}

// ---------------- conversion kernels ----------------
__global__ __launch_bounds__(256)
void split_f32(const float* __restrict__ in, __nv_bfloat16* __restrict__ hi,
               __nv_bfloat16* __restrict__ lo, size_t n4)
{
    size_t i = (size_t)blockIdx.x * blockDim.x + threadIdx.x;
    if (i >= n4) return;
    float4 v = ((const float4*)in)[i];
    __nv_bfloat16 h0 = __float2bfloat16(v.x), h1 = __float2bfloat16(v.y);
    __nv_bfloat16 h2 = __float2bfloat16(v.z), h3 = __float2bfloat16(v.w);
    __nv_bfloat16 l0 = __float2bfloat16(v.x - __bfloat162float(h0));
    __nv_bfloat16 l1 = __float2bfloat16(v.y - __bfloat162float(h1));
    __nv_bfloat16 l2 = __float2bfloat16(v.z - __bfloat162float(h2));
    __nv_bfloat16 l3 = __float2bfloat16(v.w - __bfloat162float(h3));
    ((__nv_bfloat162*)hi)[i * 2 + 0] = __nv_bfloat162(h0, h1);
    ((__nv_bfloat162*)hi)[i * 2 + 1] = __nv_bfloat162(h2, h3);
    ((__nv_bfloat162*)lo)[i * 2 + 0] = __nv_bfloat162(l0, l1);
    ((__nv_bfloat162*)lo)[i * 2 + 1] = __nv_bfloat162(l2, l3);
}

// in: [K][N] fp32 row-major -> out hi/lo: [N][K] bf16 row-major
__global__ __launch_bounds__(256)
void transpose_split(const float* __restrict__ in, __nv_bfloat16* __restrict__ hi,
                     __nv_bfloat16* __restrict__ lo, int K, int N)
{
    __shared__ float t[32][33];
    const int k0 = blockIdx.y * 32;
    const int n0 = blockIdx.x * 32;
    const int tx = threadIdx.x;
    const int ty = threadIdx.y;
#pragma unroll
    for (int r = 0; r < 4; r++) {
        const int k = k0 + ty * 4 + r;
        t[ty * 4 + r][tx] = in[(size_t)k * N + n0 + tx];
    }
    __syncthreads();
#pragma unroll
    for (int r = 0; r < 4; r++) {
        const int n = n0 + ty * 4 + r;
        const float v = t[tx][ty * 4 + r];
        const __nv_bfloat16 h = __float2bfloat16(v);
        const __nv_bfloat16 l = __float2bfloat16(v - __bfloat162float(h));
        hi[(size_t)n * K + k0 + tx] = h;
        lo[(size_t)n * K + k0 + tx] = l;
    }
}

// ---------------- heads ----------------
__global__ __launch_bounds__(256)
void heads_kernel(const float* __restrict__ H,
                  const float* __restrict__ Wc, const float* __restrict__ bc,
                  const float* __restrict__ Wr, const float* __restrict__ br,
                  float* __restrict__ out, int M)
{
    const int warp = (blockIdx.x * blockDim.x + threadIdx.x) >> 5;
    const int lane = threadIdx.x & 31;
    if (warp >= M) return;

    const float* __restrict__ h = H + (size_t)warp * D_HID;
    float acc[16];
#pragma unroll
    for (int c = 0; c < 16; c++) acc[c] = 0.0f;

    for (int k = lane; k < D_HID; k += 32) {
        const float x = h[k];
        const float* wc = Wc + (size_t)k * 4;
#pragma unroll
        for (int c = 0; c < 4; c++) acc[c] = fmaf(x, wc[c], acc[c]);
        const float* wr = Wr + (size_t)k * 12;
#pragma unroll
        for (int c = 0; c < 12; c++) acc[4 + c] = fmaf(x, wr[c], acc[4 + c]);
    }
#pragma unroll
    for (int c = 0; c < 16; c++)
#pragma unroll
        for (int off = 16; off > 0; off >>= 1)
            acc[c] += __shfl_xor_sync(0xffffffffu, acc[c], off);

    if (lane < 4) {
        out[(size_t)warp * 4 + lane] = acc[lane] + bc[lane];
    } else if (lane < 16) {
        out[(size_t)M * 4 + (size_t)warp * 12 + (lane - 4)] = acc[lane] + br[lane - 4];
    }
}

// ---------------- host ----------------
extern "C" void kernel_launch(void* const* d_in, const int* in_sizes, int n_in,
                              void* d_out, int out_size)
{
    const float* X  = (const float*)d_in[0];
    const float* W1 = (const float*)d_in[1];
    const float* b1 = (const float*)d_in[2];
    const float* W2 = (const float*)d_in[3];
    const float* b2 = (const float*)d_in[4];
    const float* Wc = (const float*)d_in[5];
    const float* bc = (const float*)d_in[6];
    const float* Wr = (const float*)d_in[7];
    const float* br = (const float*)d_in[8];
    float* out = (float*)d_out;

    const int M = in_sizes[0] / D_IN;   // 16000

    __nv_bfloat16 *Xhi, *Xlo, *W1hi, *W1lo, *W2hi, *W2lo, *h1hi, *h1lo;
    float* h2;
    cudaGetSymbolAddress((void**)&Xhi, g_Xhi);
    cudaGetSymbolAddress((void**)&Xlo, g_Xlo);
    cudaGetSymbolAddress((void**)&W1hi, g_W1hi);
    cudaGetSymbolAddress((void**)&W1lo, g_W1lo);
    cudaGetSymbolAddress((void**)&W2hi, g_W2hi);
    cudaGetSymbolAddress((void**)&W2lo, g_W2lo);
    cudaGetSymbolAddress((void**)&h1hi, g_h1hi);
    cudaGetSymbolAddress((void**)&h1lo, g_h1lo);
    cudaGetSymbolAddress((void**)&h2, g_h2);

    // conversions
    {
        const size_t n4 = (size_t)M * D_IN / 4;
        split_f32<<<(unsigned)((n4 + 255) / 256), 256>>>(X, Xhi, Xlo, n4);
        dim3 tb(32, 8);
        transpose_split<<<dim3(D_HID / 32, D_IN / 32), tb>>>(W1, W1hi, W1lo, D_IN, D_HID);
        transpose_split<<<dim3(D_HID / 32, D_HID / 32), tb>>>(W2, W2hi, W2lo, D_HID, D_HID);
    }

    cudaFuncSetAttribute(gemm_mma_x3<1>, cudaFuncAttributeMaxDynamicSharedMemorySize, SM_TOTAL);
    cudaFuncSetAttribute(gemm_mma_x3<0>, cudaFuncAttributeMaxDynamicSharedMemorySize, SM_TOTAL);

    dim3 grid(D_HID / 128, M / 128);   // (8, 125) = 1000 CTAs
    gemm_mma_x3<1><<<grid, 512, SM_TOTAL>>>(Xhi, Xlo, W1hi, W1lo, b1, h1hi, h1lo, nullptr, D_IN, D_HID);
    gemm_mma_x3<0><<<grid, 512, SM_TOTAL>>>(h1hi, h1lo, W2hi, W2lo, b2, nullptr, nullptr, h2, D_HID, D_HID);

    const int threads = 256;
    const int blocks = (M * 32 + threads - 1) / threads;
    heads_kernel<<<blocks, threads>>>(h2, Wc, bc, Wr, br, out, M);
}